// round 3
// baseline (speedup 1.0000x reference)
#include <cuda_runtime.h>
#include <math.h>

#define BB   32
#define TT   8192
#define SS   32
#define IND  128
#define HH   256
#define NTOK (BB*TT)

// output section offsets (floats): emissions, state_probs, ll, trans, best_path, path_score
#define PROBS_OFF  8388608L
#define LL_OFF     16777216L
#define TRANS_OFF  16777248L
#define BP_OFF     16778272L
#define PS_OFF     17040416L

__device__ float         g_alphas[(size_t)NTOK * SS];
__device__ unsigned char g_bp[(size_t)NTOK * SS];
__device__ float         g_trans[SS * SS];
__device__ float         g_logtrans[SS * SS];
__device__ float         g_loginit[SS];
__device__ int           g_last[BB];

__device__ __forceinline__ float gelu_exact(float v) {
    return 0.5f * v * (1.0f + erff(v * 0.70710678118654752440f));
}

// ---------------- kernel 0: params ----------------
__global__ void __launch_bounds__(1024) k_params(const float* __restrict__ il,
                                                 const float* __restrict__ tl,
                                                 float* __restrict__ trans_out)
{
    const int w = threadIdx.x >> 5, lane = threadIdx.x & 31;
    {
        float vv = tl[w * SS + lane];
        float m = vv;
        #pragma unroll
        for (int o = 16; o; o >>= 1) m = fmaxf(m, __shfl_xor_sync(~0u, m, o));
        float e = expf(vv - m), s = e;
        #pragma unroll
        for (int o = 16; o; o >>= 1) s += __shfl_xor_sync(~0u, s, o);
        float tr = e / s;
        g_trans[w * SS + lane] = tr;
        trans_out[w * SS + lane] = tr;
        g_logtrans[w * SS + lane] = logf(tr + 1e-10f);
    }
    if (w == 0) {
        float vv = il[lane];
        float m = vv;
        #pragma unroll
        for (int o = 16; o; o >>= 1) m = fmaxf(m, __shfl_xor_sync(~0u, m, o));
        float e = expf(vv - m), s = e;
        #pragma unroll
        for (int o = 16; o; o >>= 1) s += __shfl_xor_sync(~0u, s, o);
        g_loginit[lane] = logf(e / s + 1e-10f);
    }
}

// ---------------- kernel 1: fused emission MLP ----------------
// smem floats: SX[32][128] @0 | SH1[32][256] @4096 | SH2[32][256] @12288
//              WB[16][256] @20480 | MUS[32*2] @24576 ; stage C reuses @0 as W3B[256][32]
#define MLP_SMEM_BYTES (24640 * 4)

__global__ void __launch_bounds__(256) k_mlp(
    const float* __restrict__ x,
    const float* __restrict__ W1, const float* __restrict__ b1,
    const float* __restrict__ lng, const float* __restrict__ lnb,
    const float* __restrict__ W2, const float* __restrict__ b2,
    const float* __restrict__ W3, const float* __restrict__ b3,
    float* __restrict__ emis)
{
    extern __shared__ float sm[];
    float* SX  = sm;
    float* SH1 = sm + 4096;
    float* SH2 = sm + 12288;
    float* WB  = sm + 20480;
    float* MUS = sm + 24576;
    float* W3B = sm;

    const int tid = threadIdx.x;
    const int w = tid >> 5, lane = tid & 31;
    const size_t tok0 = (size_t)blockIdx.x * 32;

    {   // load x tile (32x128 fp32 = 16KB)
        const float4* xg = (const float4*)(x + tok0 * IND);
        float4* d = (float4*)SX;
        #pragma unroll
        for (int i = 0; i < 4; i++) d[tid + 256 * i] = xg[tid + 256 * i];
    }
    __syncthreads();

    float acc[4][8];
    #pragma unroll
    for (int i = 0; i < 4; i++)
        #pragma unroll
        for (int u = 0; u < 8; u++) acc[i][u] = 0.f;

    // stage A: h1 = x @ W1
    for (int kc = 0; kc < IND; kc += 16) {
        {
            const float4* wg = (const float4*)(W1 + (size_t)kc * HH);
            float4* d = (float4*)WB;
            #pragma unroll
            for (int i = 0; i < 4; i++) d[tid + 256 * i] = wg[tid + 256 * i];
        }
        __syncthreads();
        #pragma unroll
        for (int k = 0; k < 16; k++) {
            float xv[4];
            #pragma unroll
            for (int i = 0; i < 4; i++) xv[i] = SX[(4 * w + i) * IND + kc + k];
            #pragma unroll
            for (int u = 0; u < 8; u++) {
                float wv = WB[k * HH + lane + 32 * u];
                #pragma unroll
                for (int i = 0; i < 4; i++) acc[i][u] = fmaf(xv[i], wv, acc[i][u]);
            }
        }
        __syncthreads();
    }
    #pragma unroll
    for (int u = 0; u < 8; u++) {
        int jj = lane + 32 * u;
        float bbv = b1[jj];
        #pragma unroll
        for (int i = 0; i < 4; i++) SH1[(4 * w + i) * HH + jj] = acc[i][u] + bbv;
    }
    __syncthreads();

    // LayerNorm stats (each warp handles its 4 tokens)
    #pragma unroll
    for (int i = 0; i < 4; i++) {
        int t = 4 * w + i;
        float s = 0.f, ss = 0.f;
        #pragma unroll
        for (int u = 0; u < 8; u++) {
            float v = SH1[t * HH + lane + 32 * u];
            s += v; ss = fmaf(v, v, ss);
        }
        #pragma unroll
        for (int o = 16; o; o >>= 1) {
            s  += __shfl_xor_sync(~0u, s, o);
            ss += __shfl_xor_sync(~0u, ss, o);
        }
        if (lane == 0) {
            float mu = s * (1.f / HH);
            float var = ss * (1.f / HH) - mu * mu;
            MUS[2 * t] = mu;
            MUS[2 * t + 1] = rsqrtf(var + 1e-5f);
        }
    }
    __syncthreads();

    // LN transform + GELU in place
    {
        float gv = lng[tid], bv = lnb[tid];
        #pragma unroll 8
        for (int t = 0; t < 32; t++) {
            float v = SH1[t * HH + tid];
            v = (v - MUS[2 * t]) * MUS[2 * t + 1] * gv + bv;
            SH1[t * HH + tid] = gelu_exact(v);
        }
    }
    __syncthreads();

    // stage B: h2 = gelu(g1 @ W2 + b2)
    #pragma unroll
    for (int i = 0; i < 4; i++)
        #pragma unroll
        for (int u = 0; u < 8; u++) acc[i][u] = 0.f;

    for (int kc = 0; kc < HH; kc += 16) {
        {
            const float4* wg = (const float4*)(W2 + (size_t)kc * HH);
            float4* d = (float4*)WB;
            #pragma unroll
            for (int i = 0; i < 4; i++) d[tid + 256 * i] = wg[tid + 256 * i];
        }
        __syncthreads();
        #pragma unroll
        for (int k = 0; k < 16; k++) {
            float xv[4];
            #pragma unroll
            for (int i = 0; i < 4; i++) xv[i] = SH1[(4 * w + i) * HH + kc + k];
            #pragma unroll
            for (int u = 0; u < 8; u++) {
                float wv = WB[k * HH + lane + 32 * u];
                #pragma unroll
                for (int i = 0; i < 4; i++) acc[i][u] = fmaf(xv[i], wv, acc[i][u]);
            }
        }
        __syncthreads();
    }
    #pragma unroll
    for (int u = 0; u < 8; u++) {
        int jj = lane + 32 * u;
        float bbv = b2[jj];
        #pragma unroll
        for (int i = 0; i < 4; i++)
            SH2[(4 * w + i) * HH + jj] = gelu_exact(acc[i][u] + bbv);
    }
    __syncthreads();

    // stage C: logits = h2 @ W3 + b3 -> log_softmax
    {
        const float4* wg = (const float4*)W3;
        float4* d = (float4*)W3B;
        #pragma unroll
        for (int i = 0; i < 8; i++) d[tid + 256 * i] = wg[tid + 256 * i];
    }
    __syncthreads();

    float acc3[4] = {0.f, 0.f, 0.f, 0.f};
    #pragma unroll 4
    for (int k = 0; k < HH; k++) {
        float wv = W3B[k * SS + lane];
        #pragma unroll
        for (int i = 0; i < 4; i++)
            acc3[i] = fmaf(SH2[(4 * w + i) * HH + k], wv, acc3[i]);
    }
    float bbv = b3[lane];
    #pragma unroll
    for (int i = 0; i < 4; i++) {
        float v = acc3[i] + bbv;
        float m = v;
        #pragma unroll
        for (int o = 16; o; o >>= 1) m = fmaxf(m, __shfl_xor_sync(~0u, m, o));
        float e = expf(v - m), s = e;
        #pragma unroll
        for (int o = 16; o; o >>= 1) s += __shfl_xor_sync(~0u, s, o);
        emis[(tok0 + 4 * w + i) * SS + lane] = v - m - logf(s);
    }
}

// ---------------- kernel 2: forward + Viterbi scans ----------------
__global__ void __launch_bounds__(64) k_scan(const float* __restrict__ emis,
                                             float* __restrict__ ll,
                                             float* __restrict__ ps)
{
    const int b = blockIdx.x;
    const int wid = threadIdx.x >> 5;
    const int j = threadIdx.x & 31;
    const float* em = emis + (size_t)b * TT * SS;

    if (wid == 0) {
        float* alph = g_alphas + (size_t)b * TT * SS;
        float tr[32];
        #pragma unroll
        for (int i = 0; i < 32; i++) tr[i] = g_trans[i * SS + j] + 1e-10f;

        float a = g_loginit[j] + em[j];
        alph[j] = a;
        float m = a;
        #pragma unroll
        for (int o = 16; o; o >>= 1) m = fmaxf(m, __shfl_xor_sync(~0u, m, o));
        float mnext = m;

        float emA = __ldg(em + SS + j);
        float emB = __ldg(em + 2 * SS + j);
        for (int t = 1; t < TT; t++) {
            float emv = emA; emA = emB;
            int tn = (t + 2 < TT) ? (t + 2) : (TT - 1);
            emB = __ldg(em + (size_t)tn * SS + j);

            float e = __expf(a - m);  // lagged max: exact rescale, bounded args
            float s0 = 0.f, s1 = 0.f, s2 = 0.f, s3 = 0.f;
            #pragma unroll
            for (int i = 0; i < 32; i += 4) {
                s0 = fmaf(__shfl_sync(~0u, e, i    ), tr[i    ], s0);
                s1 = fmaf(__shfl_sync(~0u, e, i + 1), tr[i + 1], s1);
                s2 = fmaf(__shfl_sync(~0u, e, i + 2), tr[i + 2], s2);
                s3 = fmaf(__shfl_sync(~0u, e, i + 3), tr[i + 3], s3);
            }
            a = emv + m + __logf((s0 + s1) + (s2 + s3));
            alph[(size_t)t * SS + j] = a;

            m = mnext;                // off-critical-path max reduction
            float mm = a;
            #pragma unroll
            for (int o = 16; o; o >>= 1) mm = fmaxf(mm, __shfl_xor_sync(~0u, mm, o));
            mnext = mm;
        }
        float e = __expf(a - mnext), sum = e;
        #pragma unroll
        for (int o = 16; o; o >>= 1) sum += __shfl_xor_sync(~0u, sum, o);
        if (j == 0) ll[b] = mnext + __logf(sum);
    } else {
        unsigned char* bprow = g_bp + (size_t)b * TT * SS;
        float lt[32];
        #pragma unroll
        for (int i = 0; i < 32; i++) lt[i] = g_logtrans[i * SS + j];

        float v = g_loginit[j] + em[j];
        float emA = __ldg(em + SS + j);
        float emB = __ldg(em + 2 * SS + j);
        for (int t = 1; t < TT; t++) {
            float emv = emA; emA = emB;
            int tn = (t + 2 < TT) ? (t + 2) : (TT - 1);
            emB = __ldg(em + (size_t)tn * SS + j);

            float bv[4]; int bi[4];
            #pragma unroll
            for (int c = 0; c < 4; c++) {
                const int base = c * 8;
                float best = __shfl_sync(~0u, v, base) + lt[base];
                int idx = base;
                #pragma unroll
                for (int q = 1; q < 8; q++) {
                    float cand = __shfl_sync(~0u, v, base + q) + lt[base + q];
                    if (cand > best) { best = cand; idx = base + q; }
                }
                bv[c] = best; bi[c] = idx;
            }
            float best = bv[0]; int idx = bi[0];
            #pragma unroll
            for (int c = 1; c < 4; c++)
                if (bv[c] > best) { best = bv[c]; idx = bi[c]; }
            v = best + emv;
            bprow[(size_t)t * SS + j] = (unsigned char)idx;
        }
        float bvv = v; int bj = j;
        #pragma unroll
        for (int o = 16; o; o >>= 1) {
            float ov = __shfl_xor_sync(~0u, bvv, o);
            int   oi = __shfl_xor_sync(~0u, bj, o);
            if (ov > bvv || (ov == bvv && oi < bj)) { bvv = ov; bj = oi; }
        }
        if (j == 0) { ps[b] = bvv; g_last[b] = bj; }
    }
}

// ---------------- kernel 3: backtrace ----------------
#define BT_CHUNK 2048
#define BT_SMEM  (BT_CHUNK * SS)
__global__ void __launch_bounds__(256) k_backtrace(float* __restrict__ bp_out)
{
    extern __shared__ unsigned char sbp[];
    const int b = blockIdx.x, tid = threadIdx.x;
    const unsigned char* bp = g_bp + (size_t)b * TT * SS;

    int s = g_last[b];
    if (tid == 0) bp_out[(size_t)b * TT + TT - 1] = (float)s;

    for (int c = 3; c >= 0; c--) {
        const int4* src = (const int4*)(bp + (size_t)c * BT_CHUNK * SS);
        int4* dst = (int4*)sbp;
        #pragma unroll
        for (int i = 0; i < 16; i++) dst[tid + 256 * i] = src[tid + 256 * i];
        __syncthreads();
        if (tid == 0) {
            int tlo = c * BT_CHUNK; if (tlo < 1) tlo = 1;
            for (int t = c * BT_CHUNK + BT_CHUNK - 1; t >= tlo; t--) {
                s = sbp[(t - c * BT_CHUNK) * SS + s];
                bp_out[(size_t)b * TT + t - 1] = (float)s;
            }
        }
        __syncthreads();
    }
}

// ---------------- kernel 4: state_probs ----------------
__global__ void __launch_bounds__(256) k_probs(float* __restrict__ probs)
{
    size_t r = (size_t)blockIdx.x * 8 + (threadIdx.x >> 5);
    int lane = threadIdx.x & 31;
    float a = g_alphas[r * SS + lane];
    float m = a;
    #pragma unroll
    for (int o = 16; o; o >>= 1) m = fmaxf(m, __shfl_xor_sync(~0u, m, o));
    float e = __expf(a - m), sum = e;
    #pragma unroll
    for (int o = 16; o; o >>= 1) sum += __shfl_xor_sync(~0u, sum, o);
    probs[r * SS + lane] = e / sum;
}

extern "C" void kernel_launch(void* const* d_in, const int* in_sizes, int n_in,
                              void* d_out, int out_size)
{
    const float* x   = (const float*)d_in[0];
    const float* il  = (const float*)d_in[1];
    const float* tl  = (const float*)d_in[2];
    const float* W1  = (const float*)d_in[3];
    const float* b1  = (const float*)d_in[4];
    const float* lng = (const float*)d_in[5];
    const float* lnb = (const float*)d_in[6];
    const float* W2  = (const float*)d_in[7];
    const float* b2  = (const float*)d_in[8];
    const float* W3  = (const float*)d_in[9];
    const float* b3  = (const float*)d_in[10];
    float* out = (float*)d_out;

    static bool attr_done = false;
    if (!attr_done) {
        cudaFuncSetAttribute(k_mlp, cudaFuncAttributeMaxDynamicSharedMemorySize, MLP_SMEM_BYTES);
        cudaFuncSetAttribute(k_backtrace, cudaFuncAttributeMaxDynamicSharedMemorySize, BT_SMEM);
        attr_done = true;
    }

    k_params<<<1, 1024>>>(il, tl, out + TRANS_OFF);
    k_mlp<<<NTOK / 32, 256, MLP_SMEM_BYTES>>>(x, W1, b1, lng, lnb, W2, b2, W3, b3, out);
    k_scan<<<BB, 64>>>(out, out + LL_OFF, out + PS_OFF);
    k_backtrace<<<BB, 256, BT_SMEM>>>(out + BP_OFF);
    k_probs<<<NTOK / 8, 256>>>(out + PROBS_OFF);
}

// round 4
// speedup vs baseline: 1.4089x; 1.4089x over previous
#include <cuda_runtime.h>
#include <math.h>

#define BB   32
#define TT   8192
#define SS   32
#define IND  128
#define HH   256
#define NTOK (BB*TT)
#define NCHUNK 256                      // chunks per batch, 32 tokens each

// output section offsets (floats): emissions, state_probs, ll, trans, best_path, path_score
#define PROBS_OFF  8388608L
#define LL_OFF     16777216L
#define TRANS_OFF  16777248L
#define BP_OFF     16778272L
#define PS_OFF     17040416L

__device__ unsigned char g_bp[(size_t)NTOK * SS];
__device__ float g_trans[SS * SS];
__device__ float g_logtrans[SS * SS];
__device__ float g_loginit[SS];
__device__ int   g_last[BB];
__device__ int   g_flag[BB * NCHUNK];

__device__ __forceinline__ float gelu_exact(float v) {
    return 0.5f * v * (1.0f + erff(v * 0.70710678118654752440f));
}
__device__ __forceinline__ float wmax(float v) {
    #pragma unroll
    for (int o = 16; o; o >>= 1) v = fmaxf(v, __shfl_xor_sync(~0u, v, o));
    return v;
}
__device__ __forceinline__ float wsum(float v) {
    #pragma unroll
    for (int o = 16; o; o >>= 1) v += __shfl_xor_sync(~0u, v, o);
    return v;
}

// ---------------- kernel 0: params + flag reset ----------------
__global__ void __launch_bounds__(1024) k_params(const float* __restrict__ il,
                                                 const float* __restrict__ tl,
                                                 float* __restrict__ trans_out)
{
    const int w = threadIdx.x >> 5, lane = threadIdx.x & 31;
    for (int i = threadIdx.x; i < BB * NCHUNK; i += 1024) g_flag[i] = 0;
    {
        float vv = tl[w * SS + lane];
        float m = wmax(vv);
        float e = expf(vv - m);
        float s = wsum(e);
        float tr = e / s;
        g_trans[w * SS + lane] = tr;
        trans_out[w * SS + lane] = tr;
        g_logtrans[w * SS + lane] = logf(tr + 1e-10f);
    }
    if (w == 0) {
        float vv = il[lane];
        float m = wmax(vv);
        float e = expf(vv - m);
        float s = wsum(e);
        g_loginit[lane] = logf(e / s + 1e-10f);
    }
}

// ---------------- fused kernel: MLP producer + HMM scan consumer ----------------
// smem floats: SX[32][128] @0 | SH1[32][256] @4096 | SH2[32][256] @12288
//              WB[16][256] @20480 | MUS[32*2] @24576 ; stage C reuses @0 as W3B[256][32]
#define MLP_SMEM_BYTES (24640 * 4)

__global__ void __launch_bounds__(256) k_fused(
    const float* __restrict__ x,
    const float* __restrict__ W1, const float* __restrict__ b1,
    const float* __restrict__ lng, const float* __restrict__ lnb,
    const float* __restrict__ W2, const float* __restrict__ b2,
    const float* __restrict__ W3, const float* __restrict__ b3,
    float* emis, float* probs, float* ll, float* ps)
{
    // ================= scan blocks (consumer, blockIdx < 32) =================
    if (blockIdx.x < BB) {
        const int b = blockIdx.x;
        const int wid = threadIdx.x >> 5, j = threadIdx.x & 31;
        if (wid >= 2) return;
        const float* em = emis + (size_t)b * TT * SS;

        if (wid == 0) {
            // -------- forward scan (lagged-max rescaled) + fused state_probs --------
            float* pr = probs + (size_t)b * TT * SS;
            float tr[32];
            #pragma unroll
            for (int i = 0; i < 32; i++) tr[i] = g_trans[i * SS + j] + 1e-10f;

            float a = 0.f, m = 0.f, mnext = 0.f;
            for (int c = 0; c < NCHUNK; c++) {
                while (__ldcg(&g_flag[c * BB + b]) == 0) __nanosleep(64);
                __threadfence();
                int t0 = 32 * c;
                const int t1 = t0 + 31;
                if (c == 0) {
                    a = g_loginit[j] + __ldcg(em + j);
                    m = wmax(a);
                    mnext = m;
                    float e0 = __expf(a - m);
                    float s0 = wsum(e0);
                    pr[j] = __fdividef(e0, s0);
                    t0 = 1;
                }
                float emA = __ldcg(em + (size_t)t0 * SS + j);
                float emB = __ldcg(em + (size_t)((t0 + 1 <= t1) ? t0 + 1 : t1) * SS + j);
                for (int t = t0; t <= t1; t++) {
                    float emv = emA; emA = emB;
                    int tn = (t + 2 <= t1) ? t + 2 : t1;
                    emB = __ldcg(em + (size_t)tn * SS + j);

                    float e = __expf(a - m);   // lagged max: exact rescale, bounded args
                    float s0 = 0.f, s1 = 0.f, s2 = 0.f, s3 = 0.f;
                    #pragma unroll
                    for (int i = 0; i < 32; i += 4) {
                        s0 = fmaf(__shfl_sync(~0u, e, i    ), tr[i    ], s0);
                        s1 = fmaf(__shfl_sync(~0u, e, i + 1), tr[i + 1], s1);
                        s2 = fmaf(__shfl_sync(~0u, e, i + 2), tr[i + 2], s2);
                        s3 = fmaf(__shfl_sync(~0u, e, i + 3), tr[i + 3], s3);
                    }
                    a = emv + m + __logf((s0 + s1) + (s2 + s3));
                    m = mnext;                 // off-critical-path max reduction
                    mnext = wmax(a);
                    // fused softmax (uses exact max of current a)
                    float e2 = __expf(a - mnext);
                    float ss = wsum(e2);
                    pr[(size_t)t * SS + j] = __fdividef(e2, ss);
                }
            }
            float e = __expf(a - mnext);
            float sum = wsum(e);
            if (j == 0) ll[b] = mnext + __logf(sum);
        } else {
            // -------- Viterbi scan --------
            unsigned char* bprow = g_bp + (size_t)b * TT * SS;
            float lt[32];
            #pragma unroll
            for (int i = 0; i < 32; i++) lt[i] = g_logtrans[i * SS + j];

            float v = 0.f;
            for (int c = 0; c < NCHUNK; c++) {
                while (__ldcg(&g_flag[c * BB + b]) == 0) __nanosleep(64);
                __threadfence();
                int t0 = 32 * c;
                const int t1 = t0 + 31;
                if (c == 0) {
                    v = g_loginit[j] + __ldcg(em + j);
                    t0 = 1;
                }
                float emA = __ldcg(em + (size_t)t0 * SS + j);
                float emB = __ldcg(em + (size_t)((t0 + 1 <= t1) ? t0 + 1 : t1) * SS + j);
                for (int t = t0; t <= t1; t++) {
                    float emv = emA; emA = emB;
                    int tn = (t + 2 <= t1) ? t + 2 : t1;
                    emB = __ldcg(em + (size_t)tn * SS + j);

                    float bv[4]; int bi[4];
                    #pragma unroll
                    for (int cc = 0; cc < 4; cc++) {
                        const int base = cc * 8;
                        float best = __shfl_sync(~0u, v, base) + lt[base];
                        int idx = base;
                        #pragma unroll
                        for (int q = 1; q < 8; q++) {
                            float cand = __shfl_sync(~0u, v, base + q) + lt[base + q];
                            if (cand > best) { best = cand; idx = base + q; }
                        }
                        bv[cc] = best; bi[cc] = idx;
                    }
                    float best = bv[0]; int idx = bi[0];
                    #pragma unroll
                    for (int cc = 1; cc < 4; cc++)
                        if (bv[cc] > best) { best = bv[cc]; idx = bi[cc]; }
                    v = best + emv;
                    bprow[(size_t)t * SS + j] = (unsigned char)idx;
                }
            }
            float bvv = v; int bj = j;
            #pragma unroll
            for (int o = 16; o; o >>= 1) {
                float ov = __shfl_xor_sync(~0u, bvv, o);
                int   oi = __shfl_xor_sync(~0u, bj, o);
                if (ov > bvv || (ov == bvv && oi < bj)) { bvv = ov; bj = oi; }
            }
            if (j == 0) { ps[b] = bvv; g_last[b] = bj; }
        }
        return;
    }

    // ================= MLP blocks (producer), time-major mapping =================
    extern __shared__ float sm[];
    float* SX  = sm;
    float* SH1 = sm + 4096;
    float* SH2 = sm + 12288;
    float* WB  = sm + 20480;
    float* MUS = sm + 24576;
    float* W3B = sm;

    const int tid = threadIdx.x;
    const int w = tid >> 5, lane = tid & 31;
    const int imlp = blockIdx.x - BB;          // 0..8191
    const int cchunk = imlp >> 5;              // time chunk 0..255
    const int bb = imlp & 31;                  // batch
    const size_t tok0 = (size_t)bb * TT + 32 * (size_t)cchunk;

    {   // load x tile (32 tokens x 128 fp32)
        const float4* xg = (const float4*)(x + tok0 * IND);
        float4* d = (float4*)SX;
        #pragma unroll
        for (int i = 0; i < 4; i++) d[tid + 256 * i] = xg[tid + 256 * i];
    }

    float acc[4][8];
    #pragma unroll
    for (int i = 0; i < 4; i++)
        #pragma unroll
        for (int u = 0; u < 8; u++) acc[i][u] = 0.f;

    // ---- stage A: h1 = x @ W1 (register-prefetched weight chunks) ----
    float4 pf0, pf1, pf2, pf3;
    {
        const float4* wg = (const float4*)W1;
        pf0 = wg[tid]; pf1 = wg[tid + 256]; pf2 = wg[tid + 512]; pf3 = wg[tid + 768];
    }
    for (int kc = 0; kc < IND; kc += 16) {
        __syncthreads();                       // WB free (and SX ready on first iter)
        float4* d = (float4*)WB;
        d[tid] = pf0; d[tid + 256] = pf1; d[tid + 512] = pf2; d[tid + 768] = pf3;
        __syncthreads();
        if (kc + 16 < IND) {
            const float4* wg = (const float4*)(W1 + (size_t)(kc + 16) * HH);
            pf0 = wg[tid]; pf1 = wg[tid + 256]; pf2 = wg[tid + 512]; pf3 = wg[tid + 768];
        }
        #pragma unroll
        for (int k = 0; k < 16; k++) {
            float xv[4];
            #pragma unroll
            for (int i = 0; i < 4; i++) xv[i] = SX[(4 * w + i) * IND + kc + k];
            #pragma unroll
            for (int u = 0; u < 8; u++) {
                float wv = WB[k * HH + lane + 32 * u];
                #pragma unroll
                for (int i = 0; i < 4; i++) acc[i][u] = fmaf(xv[i], wv, acc[i][u]);
            }
        }
    }
    __syncthreads();
    #pragma unroll
    for (int u = 0; u < 8; u++) {
        int jj = lane + 32 * u;
        float bbv = b1[jj];
        #pragma unroll
        for (int i = 0; i < 4; i++) SH1[(4 * w + i) * HH + jj] = acc[i][u] + bbv;
    }
    __syncthreads();

    // ---- LayerNorm stats ----
    #pragma unroll
    for (int i = 0; i < 4; i++) {
        int t = 4 * w + i;
        float s = 0.f, ss = 0.f;
        #pragma unroll
        for (int u = 0; u < 8; u++) {
            float v = SH1[t * HH + lane + 32 * u];
            s += v; ss = fmaf(v, v, ss);
        }
        s = wsum(s); ss = wsum(ss);
        if (lane == 0) {
            float mu = s * (1.f / HH);
            float var = ss * (1.f / HH) - mu * mu;
            MUS[2 * t] = mu;
            MUS[2 * t + 1] = rsqrtf(var + 1e-5f);
        }
    }
    __syncthreads();

    // ---- LN transform + GELU in place ----
    {
        float gv = lng[tid], bv = lnb[tid];
        #pragma unroll 8
        for (int t = 0; t < 32; t++) {
            float v = SH1[t * HH + tid];
            v = (v - MUS[2 * t]) * MUS[2 * t + 1] * gv + bv;
            SH1[t * HH + tid] = gelu_exact(v);
        }
    }

    // ---- stage B: h2 = gelu(g1 @ W2 + b2) ----
    #pragma unroll
    for (int i = 0; i < 4; i++)
        #pragma unroll
        for (int u = 0; u < 8; u++) acc[i][u] = 0.f;

    {
        const float4* wg = (const float4*)W2;
        pf0 = wg[tid]; pf1 = wg[tid + 256]; pf2 = wg[tid + 512]; pf3 = wg[tid + 768];
    }
    for (int kc = 0; kc < HH; kc += 16) {
        __syncthreads();
        float4* d = (float4*)WB;
        d[tid] = pf0; d[tid + 256] = pf1; d[tid + 512] = pf2; d[tid + 768] = pf3;
        __syncthreads();
        if (kc + 16 < HH) {
            const float4* wg = (const float4*)(W2 + (size_t)(kc + 16) * HH);
            pf0 = wg[tid]; pf1 = wg[tid + 256]; pf2 = wg[tid + 512]; pf3 = wg[tid + 768];
        }
        #pragma unroll
        for (int k = 0; k < 16; k++) {
            float xv[4];
            #pragma unroll
            for (int i = 0; i < 4; i++) xv[i] = SH1[(4 * w + i) * HH + kc + k];
            #pragma unroll
            for (int u = 0; u < 8; u++) {
                float wv = WB[k * HH + lane + 32 * u];
                #pragma unroll
                for (int i = 0; i < 4; i++) acc[i][u] = fmaf(xv[i], wv, acc[i][u]);
            }
        }
    }
    __syncthreads();
    #pragma unroll
    for (int u = 0; u < 8; u++) {
        int jj = lane + 32 * u;
        float bbv = b2[jj];
        #pragma unroll
        for (int i = 0; i < 4; i++)
            SH2[(4 * w + i) * HH + jj] = gelu_exact(acc[i][u] + bbv);
    }
    __syncthreads();

    // ---- stage C: logits = h2 @ W3 + b3 -> log_softmax ----
    {
        const float4* wg = (const float4*)W3;
        float4* d = (float4*)W3B;
        #pragma unroll
        for (int i = 0; i < 8; i++) d[tid + 256 * i] = wg[tid + 256 * i];
    }
    __syncthreads();

    float acc3[4] = {0.f, 0.f, 0.f, 0.f};
    #pragma unroll 4
    for (int k = 0; k < HH; k++) {
        float wv = W3B[k * SS + lane];
        #pragma unroll
        for (int i = 0; i < 4; i++)
            acc3[i] = fmaf(SH2[(4 * w + i) * HH + k], wv, acc3[i]);
    }
    float bbv = b3[lane];
    #pragma unroll
    for (int i = 0; i < 4; i++) {
        float v = acc3[i] + bbv;
        float m = wmax(v);
        float e = expf(v - m);
        float s = wsum(e);
        emis[(tok0 + 4 * w + i) * SS + lane] = v - m - logf(s);
    }

    // ---- publish chunk to the scan consumers ----
    __threadfence();
    __syncthreads();
    if (tid == 0) atomicExch(&g_flag[imlp], 1);
}

// ---------------- backtrace: segment composition (2 short walks) ----------------
__global__ void __launch_bounds__(1024) k_backtrace(float* __restrict__ bp_out)
{
    __shared__ int comp[32][32];
    __shared__ int entry_s[32];
    const int b = blockIdx.x;
    const int seg = threadIdx.x >> 5, e = threadIdx.x & 31;
    const unsigned char* bp = g_bp + (size_t)b * TT * SS;
    const int tTop = seg * 256 + 255;

    // pass 1: per-segment transfer function for all 32 entry states
    int st = e;
    for (int t = tTop; t >= seg * 256 + 1; t--)
        st = bp[(size_t)t * SS + st];
    comp[seg][e] = st;
    __syncthreads();

    // compose segment maps (scalar)
    if (threadIdx.x == 0) {
        int cur = g_last[b];                    // path[8191]
        for (int s = 31; s >= 0; s--) {
            entry_s[s] = cur;                   // path at top index of segment s
            int ex = comp[s][cur];              // path[256*s]
            if (s > 0) cur = bp[(size_t)(256 * s) * SS + ex];   // path[256*s - 1]
        }
    }
    __syncthreads();

    // pass 2: re-walk each segment with the true entry, emit states
    if (e == 0) {
        int cur = entry_s[seg];
        float* o = bp_out + (size_t)b * TT;
        o[tTop] = (float)cur;
        for (int t = tTop; t >= seg * 256 + 1; t--) {
            cur = bp[(size_t)t * SS + cur];
            o[t - 1] = (float)cur;
        }
    }
}

extern "C" void kernel_launch(void* const* d_in, const int* in_sizes, int n_in,
                              void* d_out, int out_size)
{
    const float* x   = (const float*)d_in[0];
    const float* il  = (const float*)d_in[1];
    const float* tl  = (const float*)d_in[2];
    const float* W1  = (const float*)d_in[3];
    const float* b1  = (const float*)d_in[4];
    const float* lng = (const float*)d_in[5];
    const float* lnb = (const float*)d_in[6];
    const float* W2  = (const float*)d_in[7];
    const float* b2  = (const float*)d_in[8];
    const float* W3  = (const float*)d_in[9];
    const float* b3  = (const float*)d_in[10];
    float* out = (float*)d_out;

    static bool attr_done = false;
    if (!attr_done) {
        cudaFuncSetAttribute(k_fused, cudaFuncAttributeMaxDynamicSharedMemorySize, MLP_SMEM_BYTES);
        attr_done = true;
    }

    k_params<<<1, 1024>>>(il, tl, out + TRANS_OFF);
    k_fused<<<BB + NTOK / 32, 256, MLP_SMEM_BYTES>>>(x, W1, b1, lng, lnb, W2, b2, W3, b3,
                                                     out, out + PROBS_OFF,
                                                     out + LL_OFF, out + PS_OFF);
    k_backtrace<<<BB, 1024>>>(out + BP_OFF);
}